// round 13
// baseline (speedup 1.0000x reference)
#include <cuda_runtime.h>

// Shapes (fixed by the problem)
#define B_   8
#define C_   256
#define MID_ 16
#define H_   128
#define W_   128
#define HW_  (H_*W_)      // 16384
#define PADK 3

// Scratch (no allocs allowed)
__device__ float g_xlow0[B_*MID_*HW_];   // 8 MB : partial sum c=0..127
__device__ float g_xlow1[B_*MID_*HW_];   // 8 MB : partial sum c=128..255
__device__ float g_outlow[B_*MID_*HW_];  // 8 MB
__device__ float g_wh[B_*HW_];           // 0.5 MB : cos^2(angle)

// ---- packed f32x2 helpers (sm_103a) ----
static __device__ __forceinline__ unsigned long long pack2(float lo, float hi) {
    unsigned long long r;
    asm("mov.b64 %0, {%1, %2};" : "=l"(r) : "f"(lo), "f"(hi));
    return r;
}
static __device__ __forceinline__ void unpack2(unsigned long long v, float& lo, float& hi) {
    asm("mov.b64 {%0, %1}, %2;" : "=f"(lo), "=f"(hi) : "l"(v));
}
static __device__ __forceinline__ unsigned long long ffma2(
    unsigned long long a, unsigned long long b, unsigned long long c) {
    unsigned long long d;
    asm("fma.rn.f32x2 %0, %1, %2, %3;" : "=l"(d) : "l"(a), "l"(b), "l"(c));
    return d;
}

// ---------------------------------------------------------------------------
// K1: partial x_low.  4 px/thread x 8 m/thread (m-split x2) x c-half (x2).
// LANE SWAP: f32x2 lanes hold 2 adjacent PIXELS; weights pre-duplicated (w,w)
// in smem.  The float4 x load is consumed directly as two u64 operands ->
// zero pack instructions in the inner loop.  Explicit next-iter prefetch.
// grid (512, 2, 2): x = pixel quads, y = c-half, z = m-half. block = 64.
// ---------------------------------------------------------------------------
__global__ __launch_bounds__(64, 12) void k_reduce(const float* __restrict__ x,
                                                   const float* __restrict__ angle,
                                                   const float* __restrict__ wr) {
    __shared__ unsigned long long s_w[128*8];   // 8 KB: 128 c x 8 m, (w,w) dup
    int tid   = threadIdx.x;
    int cz    = blockIdx.y;                     // c-half: 0 or 1
    int mh    = blockIdx.z;                     // m-half: 0 or 1
    int cbase = cz * 128;
    int mbase = mh * 8;

    // duplicate-pack this (c-half, m-half)'s weights: thread t -> channels t, t+64
    #pragma unroll
    for (int cc = tid; cc < 128; cc += 64) {
        int c = cbase + cc;
        #pragma unroll
        for (int m = 0; m < 8; m++) {
            float wv = wr[(mbase + m) * C_ + c];
            s_w[cc * 8 + m] = pack2(wv, wv);
        }
    }
    __syncthreads();

    int t  = blockIdx.x * 64 + tid;      // 0..32767
    int pp = t * 4;                      // pixel quad base
    int b  = pp >> 14;
    int hw = pp & (HW_ - 1);

    const float* xp = x + (long)b * C_ * HW_ + (long)cbase * HW_ + hw;

    // acc[m][p2]: m = 0..7 (this m-half), p2 = pixel pair (px01, px23)
    unsigned long long acc[8][2];
    #pragma unroll
    for (int m = 0; m < 8; m++) { acc[m][0] = 0ULL; acc[m][1] = 0ULL; }

    // software-pipelined: cur holds channels c0..c0+3, nxt prefetches c0+4..
    float4 cur[4], nxt[4];
    #pragma unroll
    for (int u = 0; u < 4; u++)
        cur[u] = __ldcs(reinterpret_cast<const float4*>(xp + (long)u * HW_));

    #pragma unroll
    for (int c0 = 0; c0 < 128; c0 += 4) {
        if (c0 + 4 < 128) {
            #pragma unroll
            for (int u = 0; u < 4; u++)
                nxt[u] = __ldcs(reinterpret_cast<const float4*>(xp + (long)(c0 + 4 + u) * HW_));
        }
        #pragma unroll
        for (int u = 0; u < 4; u++) {
            // float4 register quad (R..R+3) used directly as two u64 operands
            const unsigned long long* v2 =
                reinterpret_cast<const unsigned long long*>(&cur[u]);
            unsigned long long vAB = v2[0];     // (px0, px1)
            unsigned long long vCD = v2[1];     // (px2, px3)
            const ulonglong2* wrow =
                reinterpret_cast<const ulonglong2*>(&s_w[(c0 + u) * 8]);
            ulonglong2 w01 = wrow[0];           // (w0,w0),(w1,w1)
            ulonglong2 w23 = wrow[1];
            ulonglong2 w45 = wrow[2];
            ulonglong2 w67 = wrow[3];
            acc[0][0]=ffma2(vAB,w01.x,acc[0][0]); acc[0][1]=ffma2(vCD,w01.x,acc[0][1]);
            acc[1][0]=ffma2(vAB,w01.y,acc[1][0]); acc[1][1]=ffma2(vCD,w01.y,acc[1][1]);
            acc[2][0]=ffma2(vAB,w23.x,acc[2][0]); acc[2][1]=ffma2(vCD,w23.x,acc[2][1]);
            acc[3][0]=ffma2(vAB,w23.y,acc[3][0]); acc[3][1]=ffma2(vCD,w23.y,acc[3][1]);
            acc[4][0]=ffma2(vAB,w45.x,acc[4][0]); acc[4][1]=ffma2(vCD,w45.x,acc[4][1]);
            acc[5][0]=ffma2(vAB,w45.y,acc[5][0]); acc[5][1]=ffma2(vCD,w45.y,acc[5][1]);
            acc[6][0]=ffma2(vAB,w67.x,acc[6][0]); acc[6][1]=ffma2(vCD,w67.x,acc[6][1]);
            acc[7][0]=ffma2(vAB,w67.y,acc[7][0]); acc[7][1]=ffma2(vCD,w67.y,acc[7][1]);
        }
        #pragma unroll
        for (int u = 0; u < 4; u++) cur[u] = nxt[u];
    }

    // write this m-half's 8 rows of the c-half partial buffer (STG.128 each)
    float* op = (cz ? g_xlow1 : g_xlow0)
              + (long)b * MID_ * HW_ + (long)mbase * HW_ + hw;
    #pragma unroll
    for (int m = 0; m < 8; m++) {
        float p0, p1, p2, p3;
        unpack2(acc[m][0], p0, p1);
        unpack2(acc[m][1], p2, p3);
        *reinterpret_cast<float4*>(op + (long)m * HW_) = make_float4(p0, p1, p2, p3);
    }

    // wh = cos^2(angle), once per pixel; one (cz, mh) combo only
    if (cz == 0 && mh == 0) {
        float4 a4 = *reinterpret_cast<const float4*>(angle + b * HW_ + hw);
        float c0v = cosf(a4.x), c1v = cosf(a4.y), c2v = cosf(a4.z), c3v = cosf(a4.w);
        *reinterpret_cast<float4*>(g_wh + pp) =
            make_float4(c0v*c0v, c1v*c1v, c2v*c2v, c3v*c3v);
    }
}

// ---------------------------------------------------------------------------
// K2: out_low = wh*(x_low (*) BASE_H) + (1-wh)*(x_low (*) BASE_V)
// x_low = g_xlow0 + g_xlow1 (summed in halo load). Separable, literal taps.
// ---------------------------------------------------------------------------
#define TILE_H 16
#define TILE_W 32
#define HALO_H (TILE_H + 6)          // 22
#define HALO_W (TILE_W + 6)          // 38

// f(a)=exp(-a^2/12.5), g(a)=exp(-a^2/2), a=-3..3
#define F0 0.48675225595997157f
#define F1 0.7261490370736909f
#define F2 0.9231163463866358f
#define F3 1.0f
#define G0 0.011108996538242306f
#define G1 0.1353352832366127f
#define G2 0.6065306597126334f
#define G3 1.0f
#define SUMF (F3 + 2.0f*(F0 + F1 + F2))
#define SUMG (G3 + 2.0f*(G0 + G1 + G2))
#define INVS (1.0f/(SUMF*SUMG + 1e-8f))

__global__ __launch_bounds__(TILE_H*TILE_W) void k_conv() {
    __shared__ float  s_t[HALO_H * HALO_W];          // raw tile + halo
    __shared__ float2 s_hf[HALO_H * TILE_W];         // (Hg, Hf) per position

    const float Fk[7] = {F0, F1, F2, F3, F2, F1, F0};
    const float Gk[7] = {G0, G1, G2, G3, G2, G1, G0};

    int tid = threadIdx.y * TILE_W + threadIdx.x;
    int bz  = blockIdx.z;             // b*16 + m
    int b   = bz >> 4;
    int h0  = blockIdx.y * TILE_H;
    int w0  = blockIdx.x * TILE_W;
    int h   = h0 + threadIdx.y, w = w0 + threadIdx.x;

    float wh = g_wh[b * HW_ + h * W_ + w];

    // load halo tile with reflect padding, summing the two c-half partials
    const float* xl0 = g_xlow0 + (long)bz * HW_;
    const float* xl1 = g_xlow1 + (long)bz * HW_;
    for (int idx = tid; idx < HALO_H * HALO_W; idx += TILE_H * TILE_W) {
        int hh = idx / HALO_W, ww = idx - hh * HALO_W;
        int gh = h0 + hh - PADK;
        int gw = w0 + ww - PADK;
        gh = gh < 0 ? -gh : (gh > H_-1 ? 2*(H_-1) - gh : gh);
        gw = gw < 0 ? -gw : (gw > W_-1 ? 2*(W_-1) - gw : gw);
        int o = gh * W_ + gw;
        s_t[idx] = xl0[o] + xl1[o];
    }
    __syncthreads();

    // stage 1: horizontal 1-D passes (g and f)
    for (int idx = tid; idx < HALO_H * TILE_W; idx += TILE_H * TILE_W) {
        int r = idx >> 5;            // row 0..21 (TILE_W == 32)
        int xw = idx & 31;
        const float* row = s_t + r * HALO_W + xw;
        float hg = 0.f, hf = 0.f;
        #pragma unroll
        for (int j = 0; j < 7; j++) {
            float v = row[j];
            hg = fmaf(v, Gk[j], hg);
            hf = fmaf(v, Fk[j], hf);
        }
        s_hf[idx] = make_float2(hg, hf);
    }
    __syncthreads();

    // stage 2: vertical 1-D passes (f on Hg, g on Hf), inv folded in
    float aH = 0.f, aV = 0.f;
    #pragma unroll
    for (int i = 0; i < 7; i++) {
        float2 hv = s_hf[(threadIdx.y + i) * TILE_W + threadIdx.x];
        aH = fmaf(hv.x, Fk[i] * INVS, aH);
        aV = fmaf(hv.y, Gk[i] * INVS, aV);
    }

    g_outlow[(long)bz * HW_ + h * W_ + w] = wh * aH + (1.f - wh) * aV;
}

// ---------------------------------------------------------------------------
// K3: out[b,c,hw] = sum_m out_low[b,m,hw] * w_expand[c,m]
// 4 px/thread (STG.128) + c-split x4.  64-thread blocks, grid (512,4)=2048.
// Weights are a direct u64 reinterpret of row-major w_expand. (R10 winner.)
// ---------------------------------------------------------------------------
__global__ __launch_bounds__(64) void k_expand(float* __restrict__ out,
                                               const float* __restrict__ we) {
    __shared__ unsigned long long s_w[64*8];    // 4 KB (this block's c-quarter)
    int tid = threadIdx.x;
    int cbase = blockIdx.y * 64;                // 0,64,128,192
    {
        const unsigned long long* we64 =
            reinterpret_cast<const unsigned long long*>(we);
        #pragma unroll
        for (int i = tid; i < 64*8; i += 64) s_w[i] = we64[cbase*8 + i];
    }
    __syncthreads();

    int t  = blockIdx.x * 64 + tid;      // 0..32767
    int pp = t * 4;                      // pixel quad base
    int b  = pp >> 14;
    int hw = pp & (HW_ - 1);

    const float* olp = g_outlow + (long)b * MID_ * HW_ + hw;

    unsigned long long olA[8], olB[8], olC[8], olD[8];
    #pragma unroll
    for (int q = 0; q < 8; q++) {
        float4 e = *reinterpret_cast<const float4*>(olp + (long)(2*q)   * HW_);
        float4 o = *reinterpret_cast<const float4*>(olp + (long)(2*q+1) * HW_);
        olA[q] = pack2(e.x, o.x);
        olB[q] = pack2(e.y, o.y);
        olC[q] = pack2(e.z, o.z);
        olD[q] = pack2(e.w, o.w);
    }

    float* op = out + (long)b * C_ * HW_ + (long)cbase * HW_ + hw;

    #pragma unroll 2
    for (int c = 0; c < 64; c++) {
        const ulonglong2* wrow = reinterpret_cast<const ulonglong2*>(&s_w[c*8]);
        ulonglong2 w01 = wrow[0];
        ulonglong2 w23 = wrow[1];
        ulonglong2 w45 = wrow[2];
        ulonglong2 w67 = wrow[3];
        unsigned long long a0=0ULL, a1=0ULL, a2=0ULL, a3=0ULL;
        a0=ffma2(olA[0],w01.x,a0); a1=ffma2(olB[0],w01.x,a1); a2=ffma2(olC[0],w01.x,a2); a3=ffma2(olD[0],w01.x,a3);
        a0=ffma2(olA[1],w01.y,a0); a1=ffma2(olB[1],w01.y,a1); a2=ffma2(olC[1],w01.y,a2); a3=ffma2(olD[1],w01.y,a3);
        a0=ffma2(olA[2],w23.x,a0); a1=ffma2(olB[2],w23.x,a1); a2=ffma2(olC[2],w23.x,a2); a3=ffma2(olD[2],w23.x,a3);
        a0=ffma2(olA[3],w23.y,a0); a1=ffma2(olB[3],w23.y,a1); a2=ffma2(olC[3],w23.y,a2); a3=ffma2(olD[3],w23.y,a3);
        a0=ffma2(olA[4],w45.x,a0); a1=ffma2(olB[4],w45.x,a1); a2=ffma2(olC[4],w45.x,a2); a3=ffma2(olD[4],w45.x,a3);
        a0=ffma2(olA[5],w45.y,a0); a1=ffma2(olB[5],w45.y,a1); a2=ffma2(olC[5],w45.y,a2); a3=ffma2(olD[5],w45.y,a3);
        a0=ffma2(olA[6],w67.x,a0); a1=ffma2(olB[6],w67.x,a1); a2=ffma2(olC[6],w67.x,a2); a3=ffma2(olD[6],w67.x,a3);
        a0=ffma2(olA[7],w67.y,a0); a1=ffma2(olB[7],w67.y,a1); a2=ffma2(olC[7],w67.y,a2); a3=ffma2(olD[7],w67.y,a3);
        float l0,h0v,l1,h1v,l2,h2v,l3,h3v;
        unpack2(a0, l0, h0v);
        unpack2(a1, l1, h1v);
        unpack2(a2, l2, h2v);
        unpack2(a3, l3, h3v);
        float4 r = make_float4(l0+h0v, l1+h1v, l2+h2v, l3+h3v);
        __stcs(reinterpret_cast<float4*>(op + (long)c * HW_), r);
    }
}

// ---------------------------------------------------------------------------
extern "C" void kernel_launch(void* const* d_in, const int* in_sizes, int n_in,
                              void* d_out, int out_size) {
    const float* x      = (const float*)d_in[0];   // (8,256,128,128)
    const float* angle  = (const float*)d_in[1];   // (8,128,128)
    const float* wr     = (const float*)d_in[2];   // (16,256)
    const float* we     = (const float*)d_in[3];   // (256,16)
    float* out          = (float*)d_out;           // (8,256,128,128)

    (void)in_sizes; (void)n_in; (void)out_size;

    dim3 rgrid(512, 2, 2);                         // quads x c-half x m-half
    k_reduce<<<rgrid, 64>>>(x, angle, wr);         // 2048 blocks

    dim3 cgrid(W_/TILE_W, H_/TILE_H, B_*MID_);     // (4, 8, 128)
    dim3 cblk(TILE_W, TILE_H);
    k_conv<<<cgrid, cblk>>>();

    dim3 egrid(512, 4);                            // pixel quads x c-quarters
    k_expand<<<egrid, 64>>>(out, we);              // 2048 blocks
}